// round 1
// baseline (speedup 1.0000x reference)
#include <cuda_runtime.h>

#define NTOK 64
#define DIM  128
#define B1N  2048
#define B2N  8192
#define RATIO 4
#define QSCALE 0.17677669529663687f
#define X_ELEMS 16777216   // B1N*NTOK*DIM

// Scratch for precomputed scaled Q (B1, N, C) = 67 MB
__device__ float g_Q[B1N * NTOK * DIM];

// ---------------------------------------------------------------------------
// Kernel A: Q = scale * (x1 @ W1^T + b1)   per-window 64x128x128 GEMM
// ---------------------------------------------------------------------------
__global__ void __launch_bounds__(256) q_kernel(
    const float* __restrict__ x1, const float* __restrict__ w1,
    const float* __restrict__ bias1)
{
    __shared__ float xT[DIM * 68];   // [c][n], pad 68
    __shared__ float wT[16 * 132];   // [kk][j], pad 132

    const int t  = threadIdx.x;
    const int b  = blockIdx.x;
    const int ty = t >> 5, tx = t & 31;

    const float* xb = x1 + (size_t)b * (NTOK * DIM);
    for (int idx = t; idx < NTOK * DIM; idx += 256) {
        int n = idx >> 7, c = idx & 127;
        xT[c * 68 + n] = xb[idx];
    }

    float acc[8][4];
#pragma unroll
    for (int i = 0; i < 8; i++)
#pragma unroll
        for (int j = 0; j < 4; j++) acc[i][j] = 0.f;

    for (int k0 = 0; k0 < DIM; k0 += 16) {
        __syncthreads();
        for (int idx = t; idx < DIM * 16; idx += 256) {
            int j = idx >> 4, kk = idx & 15;
            wT[kk * 132 + j] = w1[j * DIM + k0 + kk];
        }
        __syncthreads();
#pragma unroll
        for (int kk = 0; kk < 16; kk++) {
            const float4 a0 = *(const float4*)&xT[(k0 + kk) * 68 + ty * 8];
            const float4 a1 = *(const float4*)&xT[(k0 + kk) * 68 + ty * 8 + 4];
            const float4 bv = *(const float4*)&wT[kk * 132 + tx * 4];
            const float av[8] = {a0.x, a0.y, a0.z, a0.w, a1.x, a1.y, a1.z, a1.w};
            const float bb[4] = {bv.x, bv.y, bv.z, bv.w};
#pragma unroll
            for (int i = 0; i < 8; i++)
#pragma unroll
                for (int j = 0; j < 4; j++) acc[i][j] += av[i] * bb[j];
        }
    }

    const float bb0 = bias1[tx * 4 + 0], bb1 = bias1[tx * 4 + 1];
    const float bb2 = bias1[tx * 4 + 2], bb3 = bias1[tx * 4 + 3];
    float* qb = g_Q + (size_t)b * (NTOK * DIM);
#pragma unroll
    for (int i = 0; i < 8; i++) {
        float4 o;
        o.x = (acc[i][0] + bb0) * QSCALE;
        o.y = (acc[i][1] + bb1) * QSCALE;
        o.z = (acc[i][2] + bb2) * QSCALE;
        o.w = (acc[i][3] + bb3) * QSCALE;
        *(float4*)&qb[(ty * 8 + i) * DIM + tx * 4] = o;
    }
}

// ---------------------------------------------------------------------------
// Kernel B: one CTA per output window b1. For r = 0..3:
//   b2 = b1*4 + r ; q = g_Q[b2 % 2048]
//   k,v = x2[b2] @ W2^T + b2bias ; attn = softmax(q k^T + bias) -> d_out
//   oacc += attn @ v
// then x[b1] = oacc @ Wp^T + pb -> d_out
// ---------------------------------------------------------------------------
// shared layout (float offsets):
#define SM_Q   0        // 64*132  = 8448
#define SM_K   8448     // 64*128  = 8192
#define SM_V   16640    // 64*128  = 8192
#define SM_REL 24832    // 64*65   = 4160 (int)
#define SM_TAB 28992    // 225*4   = 900
#define SM_U   29952    // union: x2T(128*68=8704)+w2T(32*260=8320)  |  oT(8704)+pwT(32*132)
#define SMB_FLOATS (29952 + 8704 + 8320)   // 46976 floats = 187904 bytes

__global__ void __launch_bounds__(256) attn_kernel(
    const float* __restrict__ x2,
    const float* __restrict__ w2, const float* __restrict__ bias2,
    const float* __restrict__ pw, const float* __restrict__ pb,
    const float* __restrict__ rpb, const int* __restrict__ rel,
    float* __restrict__ out)
{
    extern __shared__ float sm[];
    float* q_s  = sm + SM_Q;
    float* k_s  = sm + SM_K;
    float* v_s  = sm + SM_V;
    int*   rel_s = (int*)(sm + SM_REL);
    float* tab_s = sm + SM_TAB;
    float* x2T = sm + SM_U;
    float* w2T = sm + SM_U + 8704;
    float* oT  = sm + SM_U;          // aliases x2T (used after r-loop)
    float* pwT = sm + SM_U + 8704;   // aliases w2T

    const int t    = threadIdx.x;
    const int bdst = blockIdx.x;
    const int ty = t >> 5, tx = t & 31;
    const int h  = t >> 6, n  = t & 63;

    for (int idx = t; idx < NTOK * NTOK; idx += 256)
        rel_s[(idx >> 6) * 65 + (idx & 63)] = rel[idx];
    for (int idx = t; idx < 225 * 4; idx += 256)
        tab_s[idx] = rpb[idx];

    float kvb[8];
#pragma unroll
    for (int jj = 0; jj < 8; jj++) kvb[jj] = bias2[tx * 8 + jj];

    float oacc[32];
#pragma unroll
    for (int dd = 0; dd < 32; dd++) oacc[dd] = 0.f;

    for (int r = 0; r < RATIO; r++) {
        const int b2 = bdst * RATIO + r;
        const int qb = b2 & (B1N - 1);

        __syncthreads();   // previous iteration's readers of q_s/k_s/v_s done

        // stage Q window (float4, conflict-free)
        const float4* qg = (const float4*)(g_Q + (size_t)qb * (NTOK * DIM));
        for (int idx = t; idx < NTOK * DIM / 4; idx += 256) {
            int nn = idx >> 5, c4 = idx & 31;
            *(float4*)&q_s[nn * 132 + c4 * 4] = qg[idx];
        }
        // stage x2 transposed [c][n]
        const float* xb = x2 + (size_t)b2 * (NTOK * DIM);
        for (int idx = t; idx < NTOK * DIM; idx += 256) {
            int nn = idx >> 7, cc = idx & 127;
            x2T[cc * 68 + nn] = xb[idx];
        }

        // ---- kv GEMM: 64x256x128, micro-tile 8x8 per thread ----
        float kv[8][8];
#pragma unroll
        for (int i = 0; i < 8; i++)
#pragma unroll
            for (int j = 0; j < 8; j++) kv[i][j] = 0.f;

        for (int k0 = 0; k0 < DIM; k0 += 32) {
            __syncthreads();
            for (int idx = t; idx < 256 * 32; idx += 256) {
                int j = idx >> 5, kk = idx & 31;
                w2T[kk * 260 + j] = w2[j * DIM + k0 + kk];
            }
            __syncthreads();
#pragma unroll
            for (int kk = 0; kk < 32; kk++) {
                const float4 a0 = *(const float4*)&x2T[(k0 + kk) * 68 + ty * 8];
                const float4 a1 = *(const float4*)&x2T[(k0 + kk) * 68 + ty * 8 + 4];
                const float4 b0 = *(const float4*)&w2T[kk * 260 + tx * 8];
                const float4 b1 = *(const float4*)&w2T[kk * 260 + tx * 8 + 4];
                const float av[8] = {a0.x, a0.y, a0.z, a0.w, a1.x, a1.y, a1.z, a1.w};
                const float bv[8] = {b0.x, b0.y, b0.z, b0.w, b1.x, b1.y, b1.z, b1.w};
#pragma unroll
                for (int i = 0; i < 8; i++)
#pragma unroll
                    for (int j = 0; j < 8; j++) kv[i][j] += av[i] * bv[j];
            }
        }
        // scatter to k_s / v_s (+bias)
#pragma unroll
        for (int i = 0; i < 8; i++) {
            const int row = ty * 8 + i;
#pragma unroll
            for (int jj = 0; jj < 8; jj++) {
                const int j = tx * 8 + jj;
                const float val = kv[i][jj] + kvb[jj];
                if (j < DIM) k_s[row * DIM + j] = val;
                else         v_s[row * DIM + (j - DIM)] = val;
            }
        }
        __syncthreads();

        // ---- attention: thread owns row (h, n) ----
        float qreg[32];
#pragma unroll
        for (int c4 = 0; c4 < 8; c4++) {
            const float4 qv = *(const float4*)&q_s[n * 132 + h * 32 + c4 * 4];
            qreg[c4 * 4 + 0] = qv.x; qreg[c4 * 4 + 1] = qv.y;
            qreg[c4 * 4 + 2] = qv.z; qreg[c4 * 4 + 3] = qv.w;
        }

        float l[64];
#pragma unroll
        for (int m = 0; m < 64; m++) {
            float dot = 0.f;
#pragma unroll
            for (int c4 = 0; c4 < 8; c4++) {
                const float4 kvv = *(const float4*)&k_s[m * DIM + h * 32 + c4 * 4];
                dot += qreg[c4 * 4 + 0] * kvv.x + qreg[c4 * 4 + 1] * kvv.y
                     + qreg[c4 * 4 + 2] * kvv.z + qreg[c4 * 4 + 3] * kvv.w;
            }
            const int ridx = rel_s[n * 65 + m];
            l[m] = dot + tab_s[ridx * 4 + h];
        }

        // softmax (in-register, per-row)
        float mx = -1e30f;
#pragma unroll
        for (int m = 0; m < 64; m++) mx = fmaxf(mx, l[m]);
        float ssum = 0.f;
#pragma unroll
        for (int m = 0; m < 64; m++) { l[m] = __expf(l[m] - mx); ssum += l[m]; }
        const float inv = 1.f / ssum;
#pragma unroll
        for (int m = 0; m < 64; m++) l[m] *= inv;

        // write attn: out[X_ELEMS + b2*H*N*N + (h*N + n)*N + m]
        float* ao = out + (size_t)X_ELEMS + (size_t)b2 * (4 * 64 * 64) + (size_t)t * 64;
#pragma unroll
        for (int m4 = 0; m4 < 16; m4++) {
            float4 o = make_float4(l[m4 * 4 + 0], l[m4 * 4 + 1],
                                   l[m4 * 4 + 2], l[m4 * 4 + 3]);
            *(float4*)&ao[m4 * 4] = o;
        }

        // oacc += attn @ v
#pragma unroll
        for (int m = 0; m < 64; m++) {
            const float p = l[m];
#pragma unroll
            for (int c4 = 0; c4 < 8; c4++) {
                const float4 vv = *(const float4*)&v_s[m * DIM + h * 32 + c4 * 4];
                oacc[c4 * 4 + 0] += p * vv.x;
                oacc[c4 * 4 + 1] += p * vv.y;
                oacc[c4 * 4 + 2] += p * vv.z;
                oacc[c4 * 4 + 3] += p * vv.w;
            }
        }
    } // r

    // ---- output projection: x = oacc_sum @ Wp^T + pb ----
    __syncthreads();
#pragma unroll
    for (int dd = 0; dd < 32; dd++)
        oT[(h * 32 + dd) * 68 + n] = oacc[dd];

    float pacc[8][4];
#pragma unroll
    for (int i = 0; i < 8; i++)
#pragma unroll
        for (int j = 0; j < 4; j++) pacc[i][j] = 0.f;

    for (int k0 = 0; k0 < DIM; k0 += 32) {
        __syncthreads();
        for (int idx = t; idx < DIM * 32; idx += 256) {
            int j = idx >> 5, kk = idx & 31;
            pwT[kk * 132 + j] = pw[j * DIM + k0 + kk];
        }
        __syncthreads();
#pragma unroll
        for (int kk = 0; kk < 32; kk++) {
            const float4 a0 = *(const float4*)&oT[(k0 + kk) * 68 + ty * 8];
            const float4 a1 = *(const float4*)&oT[(k0 + kk) * 68 + ty * 8 + 4];
            const float4 bv = *(const float4*)&pwT[kk * 132 + tx * 4];
            const float av[8] = {a0.x, a0.y, a0.z, a0.w, a1.x, a1.y, a1.z, a1.w};
            const float bb[4] = {bv.x, bv.y, bv.z, bv.w};
#pragma unroll
            for (int i = 0; i < 8; i++)
#pragma unroll
                for (int j = 0; j < 4; j++) pacc[i][j] += av[i] * bb[j];
        }
    }

    const float pb0 = pb[tx * 4 + 0], pb1 = pb[tx * 4 + 1];
    const float pb2 = pb[tx * 4 + 2], pb3 = pb[tx * 4 + 3];
    float* xo = out + (size_t)bdst * (NTOK * DIM);
#pragma unroll
    for (int i = 0; i < 8; i++) {
        float4 o;
        o.x = pacc[i][0] + pb0;
        o.y = pacc[i][1] + pb1;
        o.z = pacc[i][2] + pb2;
        o.w = pacc[i][3] + pb3;
        *(float4*)&xo[(ty * 8 + i) * DIM + tx * 4] = o;
    }
}

// ---------------------------------------------------------------------------
extern "C" void kernel_launch(void* const* d_in, const int* in_sizes, int n_in,
                              void* d_out, int out_size)
{
    const float* x1     = (const float*)d_in[0];
    const float* x2     = (const float*)d_in[1];
    const float* qkv1_w = (const float*)d_in[2];
    const float* qkv1_b = (const float*)d_in[3];
    const float* qkv2_w = (const float*)d_in[4];
    const float* qkv2_b = (const float*)d_in[5];
    const float* proj_w = (const float*)d_in[6];
    const float* proj_b = (const float*)d_in[7];
    const float* rpb    = (const float*)d_in[8];
    const int*   rel    = (const int*)d_in[9];
    float* out = (float*)d_out;

    static bool attr_set = false;
    if (!attr_set) {
        cudaFuncSetAttribute(attn_kernel,
                             cudaFuncAttributeMaxDynamicSharedMemorySize,
                             SMB_FLOATS * sizeof(float));
        attr_set = true;
    }

    q_kernel<<<B1N, 256>>>(x1, qkv1_w, qkv1_b);
    attn_kernel<<<B1N, 256, SMB_FLOATS * sizeof(float)>>>(
        x2, qkv2_w, qkv2_b, proj_w, proj_b, rpb, rel, out);
}

// round 3
// speedup vs baseline: 1.5206x; 1.5206x over previous
#include <cuda_runtime.h>
#include <cstdint>

#define NTOK 64
#define DIM  128
#define B1N  2048
#define B2N  8192
#define QSCALE 0.17677669529663687f
#define X_ELEMS 16777216   // B1N*NTOK*DIM

// Scratch: precomputed scaled Q (B1,N,C) and KV = x2@W2^T+b (B2,N,2C)
__device__ float g_Q[B1N * NTOK * DIM];
__device__ float g_KV[(size_t)B2N * NTOK * 256];

__device__ __forceinline__ float to_tf32(float x) {
    float r; asm("cvt.rna.tf32.f32 %0, %1;" : "=f"(r) : "f"(x)); return r;
}
__device__ __forceinline__ void mma_tf32(float c[4],
    uint32_t a0, uint32_t a1, uint32_t a2, uint32_t a3,
    uint32_t b0, uint32_t b1)
{
    asm volatile(
        "mma.sync.aligned.m16n8k8.row.col.f32.tf32.tf32.f32 "
        "{%0,%1,%2,%3},{%4,%5,%6,%7},{%8,%9},{%0,%1,%2,%3};"
        : "+f"(c[0]), "+f"(c[1]), "+f"(c[2]), "+f"(c[3])
        : "r"(a0), "r"(a1), "r"(a2), "r"(a3), "r"(b0), "r"(b1));
}

// ---------------------------------------------------------------------------
// Kernel A: Q = scale * (x1 @ W1^T + b1)  (fp32)
// ---------------------------------------------------------------------------
__global__ void __launch_bounds__(256) q_kernel(
    const float* __restrict__ x1, const float* __restrict__ w1,
    const float* __restrict__ bias1)
{
    __shared__ float xT[DIM * 68];
    __shared__ float wT[16 * 132];

    const int t  = threadIdx.x;
    const int b  = blockIdx.x;
    const int ty = t >> 5, tx = t & 31;

    const float* xb = x1 + (size_t)b * (NTOK * DIM);
    for (int idx = t; idx < NTOK * DIM; idx += 256) {
        int n = idx >> 7, c = idx & 127;
        xT[c * 68 + n] = xb[idx];
    }

    float acc[8][4];
#pragma unroll
    for (int i = 0; i < 8; i++)
#pragma unroll
        for (int j = 0; j < 4; j++) acc[i][j] = 0.f;

    for (int k0 = 0; k0 < DIM; k0 += 16) {
        __syncthreads();
        for (int idx = t; idx < DIM * 16; idx += 256) {
            int j = idx >> 4, kk = idx & 15;
            wT[kk * 132 + j] = w1[j * DIM + k0 + kk];
        }
        __syncthreads();
#pragma unroll
        for (int kk = 0; kk < 16; kk++) {
            const float4 a0 = *(const float4*)&xT[(k0 + kk) * 68 + ty * 8];
            const float4 a1 = *(const float4*)&xT[(k0 + kk) * 68 + ty * 8 + 4];
            const float4 bv = *(const float4*)&wT[kk * 132 + tx * 4];
            const float av[8] = {a0.x, a0.y, a0.z, a0.w, a1.x, a1.y, a1.z, a1.w};
            const float bb[4] = {bv.x, bv.y, bv.z, bv.w};
#pragma unroll
            for (int i = 0; i < 8; i++)
#pragma unroll
                for (int j = 0; j < 4; j++) acc[i][j] += av[i] * bb[j];
        }
    }

    const float bb0 = bias1[tx * 4 + 0], bb1 = bias1[tx * 4 + 1];
    const float bb2 = bias1[tx * 4 + 2], bb3 = bias1[tx * 4 + 3];
    float* qb = g_Q + (size_t)b * (NTOK * DIM);
#pragma unroll
    for (int i = 0; i < 8; i++) {
        float4 o;
        o.x = (acc[i][0] + bb0) * QSCALE;
        o.y = (acc[i][1] + bb1) * QSCALE;
        o.z = (acc[i][2] + bb2) * QSCALE;
        o.w = (acc[i][3] + bb3) * QSCALE;
        *(float4*)&qb[(ty * 8 + i) * DIM + tx * 4] = o;
    }
}

// ---------------------------------------------------------------------------
// Kernel B: KV[b2] = x2[b2] @ W2^T + b2  via tf32 mma.sync (64x256x128)
// ---------------------------------------------------------------------------
#define KV_SMEM_FLOATS (8448 + 9216)   // a_s[64][132] + w_s[256][36]

__global__ void __launch_bounds__(256) kv_kernel(
    const float* __restrict__ x2, const float* __restrict__ w2,
    const float* __restrict__ bias2)
{
    extern __shared__ float sm[];
    float* a_s = sm;           // [m][k] stride 132 (tf32-rounded)
    float* w_s = sm + 8448;    // [j][kk] stride 36, one 32-wide k-chunk

    const int t = threadIdx.x, b2 = blockIdx.x;
    const int lane = t & 31, wid = t >> 5;
    const int m_base = (wid & 3) * 16;
    const int n_base = (wid >> 2) * 128;
    const int r0 = lane >> 2, cth = lane & 3;

    const float* xb = x2 + (size_t)b2 * (NTOK * DIM);
    for (int idx = t; idx < NTOK * DIM; idx += 256) {
        int m = idx >> 7, k = idx & 127;
        a_s[m * 132 + k] = to_tf32(xb[idx]);
    }

    float c[16][4];
#pragma unroll
    for (int nt = 0; nt < 16; nt++)
#pragma unroll
        for (int j = 0; j < 4; j++) c[nt][j] = 0.f;

    for (int kc = 0; kc < 4; kc++) {
        __syncthreads();
        for (int idx = t; idx < 8192; idx += 256) {
            int j = idx >> 5, kk = idx & 31;
            w_s[j * 36 + kk] = to_tf32(w2[j * DIM + kc * 32 + kk]);
        }
        __syncthreads();
#pragma unroll
        for (int ks = 0; ks < 4; ks++) {
            const int col = kc * 32 + ks * 8 + cth;
            const uint32_t a0 = __float_as_uint(a_s[(m_base + r0) * 132 + col]);
            const uint32_t a1 = __float_as_uint(a_s[(m_base + r0 + 8) * 132 + col]);
            const uint32_t a2 = __float_as_uint(a_s[(m_base + r0) * 132 + col + 4]);
            const uint32_t a3 = __float_as_uint(a_s[(m_base + r0 + 8) * 132 + col + 4]);
#pragma unroll
            for (int nt = 0; nt < 16; nt++) {
                const int j = n_base + nt * 8 + r0;
                const uint32_t b0 = __float_as_uint(w_s[j * 36 + ks * 8 + cth]);
                const uint32_t b1 = __float_as_uint(w_s[j * 36 + ks * 8 + 4 + cth]);
                mma_tf32(c[nt], a0, a1, a2, a3, b0, b1);
            }
        }
    }

    float* dst = g_KV + (size_t)b2 * (NTOK * 256);
    const int row0 = m_base + r0;
#pragma unroll
    for (int nt = 0; nt < 16; nt++) {
        const int col0 = n_base + nt * 8 + 2 * cth;
        const float2 bv = *(const float2*)(bias2 + col0);
        *(float2*)(dst + (size_t)row0 * 256 + col0) =
            make_float2(c[nt][0] + bv.x, c[nt][1] + bv.y);
        *(float2*)(dst + (size_t)(row0 + 8) * 256 + col0) =
            make_float2(c[nt][2] + bv.x, c[nt][3] + bv.y);
    }
}

// ---------------------------------------------------------------------------
// Kernel C: fused attention per b1. 512 threads: thread=(h,n,half).
// smem layout FIXED: rel_s needs 2048 floats (4096 uint16).
// ---------------------------------------------------------------------------
#define SM_Q   0        // q_s [n][c] stride 136 : 8704   (aliased by oT [c][n] 128x68)
#define SM_K   8704     // k_s [m][d] 64x128 : 8192       (aliased by pwT 32x132=4224)
#define SM_V   16896    // v_s 64x128 : 8192
#define SM_REL 25088    // uint16[64*64] = 8192 bytes : 2048 floats
#define SM_TAB 27136    // 225*4 : 900
#define ATTN_SMEM_FLOATS 28036

__global__ void __launch_bounds__(512, 1) attn_kernel(
    const float* __restrict__ pw, const float* __restrict__ pb,
    const float* __restrict__ rpb, const int* __restrict__ rel,
    float* __restrict__ out)
{
    extern __shared__ float sm[];
    float*    q_s   = sm + SM_Q;
    float*    k_s   = sm + SM_K;
    float*    v_s   = sm + SM_V;
    uint16_t* rel_s = (uint16_t*)(sm + SM_REL);
    float*    tab_s = sm + SM_TAB;
    float*    oT    = sm + SM_Q;    // reuse after attention
    float*    pwT   = sm + SM_K;

    const int t    = threadIdx.x;
    const int bdst = blockIdx.x;
    const int pid  = t >> 1;          // 0..255
    const int half = t & 1;
    const int h    = pid >> 6;        // 0..3
    const int n    = pid & 63;        // 0..63
    const int m0   = half * 32;

    for (int idx = t; idx < NTOK * NTOK; idx += 512)
        rel_s[idx] = (uint16_t)rel[idx];
    for (int idx = t; idx < 225 * 4; idx += 512)
        tab_s[idx] = rpb[idx];

    float oacc[32];
#pragma unroll
    for (int d = 0; d < 32; d++) oacc[d] = 0.f;

    for (int r = 0; r < 4; r++) {
        const int b2 = bdst * 4 + r;
        const int qb = b2 & (B1N - 1);

        __syncthreads();   // previous iteration readers done

        // stage Q (64x128 -> stride 136)
        const float4* qg = (const float4*)(g_Q + (size_t)qb * (NTOK * DIM));
        for (int idx = t; idx < 2048; idx += 512) {
            int nn = idx >> 5, c4 = idx & 31;
            *(float4*)&q_s[nn * 136 + c4 * 4] = qg[idx];
        }
        // stage K,V from g_KV[b2] (64x256: first 128 = K, last 128 = V)
        const float4* kvg = (const float4*)(g_KV + (size_t)b2 * (NTOK * 256));
        for (int idx = t; idx < 4096; idx += 512) {
            int m = idx >> 6, j4 = idx & 63;
            float4 v = kvg[idx];
            if (j4 < 32) *(float4*)&k_s[m * 128 + j4 * 4] = v;
            else         *(float4*)&v_s[m * 128 + (j4 - 32) * 4] = v;
        }
        __syncthreads();

        // q row into registers
        float qreg[32];
#pragma unroll
        for (int c4 = 0; c4 < 8; c4++) {
            const float4 qv = *(const float4*)&q_s[n * 136 + h * 32 + c4 * 4];
            qreg[c4 * 4 + 0] = qv.x; qreg[c4 * 4 + 1] = qv.y;
            qreg[c4 * 4 + 2] = qv.z; qreg[c4 * 4 + 3] = qv.w;
        }

        // logits for this half-row
        float l[32];
#pragma unroll
        for (int mi = 0; mi < 32; mi++) {
            const int m = m0 + mi;
            float dot = 0.f;
#pragma unroll
            for (int c4 = 0; c4 < 8; c4++) {
                const float4 kv = *(const float4*)&k_s[m * 128 + h * 32 + c4 * 4];
                dot += qreg[c4 * 4 + 0] * kv.x + qreg[c4 * 4 + 1] * kv.y
                     + qreg[c4 * 4 + 2] * kv.z + qreg[c4 * 4 + 3] * kv.w;
            }
            l[mi] = dot + tab_s[(int)rel_s[n * 64 + m] * 4 + h];
        }

        // softmax across the pair of half-threads (lanes t, t^1)
        float mx = -1e30f;
#pragma unroll
        for (int mi = 0; mi < 32; mi++) mx = fmaxf(mx, l[mi]);
        mx = fmaxf(mx, __shfl_xor_sync(0xffffffffu, mx, 1));
        float ssum = 0.f;
#pragma unroll
        for (int mi = 0; mi < 32; mi++) { l[mi] = __expf(l[mi] - mx); ssum += l[mi]; }
        ssum += __shfl_xor_sync(0xffffffffu, ssum, 1);
        const float inv = 1.f / ssum;
#pragma unroll
        for (int mi = 0; mi < 32; mi++) l[mi] *= inv;

        // write attn probs
        float* ao = out + (size_t)X_ELEMS + (size_t)b2 * 16384 + pid * 64 + m0;
#pragma unroll
        for (int m4 = 0; m4 < 8; m4++)
            *(float4*)&ao[m4 * 4] = make_float4(l[m4 * 4 + 0], l[m4 * 4 + 1],
                                                l[m4 * 4 + 2], l[m4 * 4 + 3]);

        // oacc += attn_half @ v
#pragma unroll
        for (int mi = 0; mi < 32; mi++) {
            const float p = l[mi];
            const int m = m0 + mi;
#pragma unroll
            for (int c4 = 0; c4 < 8; c4++) {
                const float4 vv = *(const float4*)&v_s[m * 128 + h * 32 + c4 * 4];
                oacc[c4 * 4 + 0] += p * vv.x;
                oacc[c4 * 4 + 1] += p * vv.y;
                oacc[c4 * 4 + 2] += p * vv.z;
                oacc[c4 * 4 + 3] += p * vv.w;
            }
        }
    } // r

    // combine halves, park in smem transposed [c][n]
#pragma unroll
    for (int d = 0; d < 32; d++)
        oacc[d] += __shfl_xor_sync(0xffffffffu, oacc[d], 1);
    __syncthreads();
    if (half == 0) {
#pragma unroll
        for (int d = 0; d < 32; d++)
            oT[(h * 32 + d) * 68 + n] = oacc[d];
    }

    // output projection: 512 threads, micro-tile 4x4
    const int ty = t >> 5, tx = t & 31;
    float pacc[4][4];
#pragma unroll
    for (int i = 0; i < 4; i++)
#pragma unroll
        for (int j = 0; j < 4; j++) pacc[i][j] = 0.f;

    for (int k0 = 0; k0 < DIM; k0 += 32) {
        __syncthreads();
        for (int idx = t; idx < DIM * 32; idx += 512) {
            int j = idx >> 5, kk = idx & 31;
            pwT[kk * 132 + j] = pw[j * DIM + k0 + kk];
        }
        __syncthreads();
#pragma unroll
        for (int kk = 0; kk < 32; kk++) {
            const float4 a4 = *(const float4*)&oT[(k0 + kk) * 68 + ty * 4];
            const float4 b4 = *(const float4*)&pwT[kk * 132 + tx * 4];
            const float av[4] = {a4.x, a4.y, a4.z, a4.w};
            const float bv[4] = {b4.x, b4.y, b4.z, b4.w};
#pragma unroll
            for (int i = 0; i < 4; i++)
#pragma unroll
                for (int j = 0; j < 4; j++) pacc[i][j] += av[i] * bv[j];
        }
    }

    const float pb0 = pb[tx * 4 + 0], pb1 = pb[tx * 4 + 1];
    const float pb2 = pb[tx * 4 + 2], pb3 = pb[tx * 4 + 3];
    float* xo = out + (size_t)bdst * (NTOK * DIM);
#pragma unroll
    for (int i = 0; i < 4; i++) {
        float4 o;
        o.x = pacc[i][0] + pb0;
        o.y = pacc[i][1] + pb1;
        o.z = pacc[i][2] + pb2;
        o.w = pacc[i][3] + pb3;
        *(float4*)&xo[(ty * 4 + i) * DIM + tx * 4] = o;
    }
}

// ---------------------------------------------------------------------------
extern "C" void kernel_launch(void* const* d_in, const int* in_sizes, int n_in,
                              void* d_out, int out_size)
{
    const float* x1     = (const float*)d_in[0];
    const float* x2     = (const float*)d_in[1];
    const float* qkv1_w = (const float*)d_in[2];
    const float* qkv1_b = (const float*)d_in[3];
    const float* qkv2_w = (const float*)d_in[4];
    const float* qkv2_b = (const float*)d_in[5];
    const float* proj_w = (const float*)d_in[6];
    const float* proj_b = (const float*)d_in[7];
    const float* rpb    = (const float*)d_in[8];
    const int*   rel    = (const int*)d_in[9];
    float* out = (float*)d_out;

    static bool attr_set = false;
    if (!attr_set) {
        cudaFuncSetAttribute(kv_kernel,
                             cudaFuncAttributeMaxDynamicSharedMemorySize,
                             KV_SMEM_FLOATS * sizeof(float));
        cudaFuncSetAttribute(attn_kernel,
                             cudaFuncAttributeMaxDynamicSharedMemorySize,
                             ATTN_SMEM_FLOATS * sizeof(float));
        attr_set = true;
    }

    q_kernel<<<B1N, 256>>>(x1, qkv1_w, qkv1_b);
    kv_kernel<<<B2N, 256, KV_SMEM_FLOATS * sizeof(float)>>>(x2, qkv2_w, qkv2_b);
    attn_kernel<<<B1N, 512, ATTN_SMEM_FLOATS * sizeof(float)>>>(
        proj_w, proj_b, rpb, rel, out);
}

// round 6
// speedup vs baseline: 2.4387x; 1.6038x over previous
#include <cuda_runtime.h>
#include <cstdint>

#define NTOK 64
#define DIM  128
#define B1N  2048
#define B2N  8192
#define QSCALE 0.17677669529663687f
#define X_ELEMS 16777216   // B1N*NTOK*DIM

__device__ float g_Q[B1N * NTOK * DIM];                 // tf32-rounded, scaled
__device__ float g_KV[(size_t)B2N * NTOK * 256];        // tf32-rounded K|V

__device__ __forceinline__ float to_tf32(float x) {
    float r; asm("cvt.rna.tf32.f32 %0, %1;" : "=f"(r) : "f"(x)); return r;
}
__device__ __forceinline__ void mma_tf32(float c[4],
    uint32_t a0, uint32_t a1, uint32_t a2, uint32_t a3,
    uint32_t b0, uint32_t b1)
{
    asm volatile(
        "mma.sync.aligned.m16n8k8.row.col.f32.tf32.tf32.f32 "
        "{%0,%1,%2,%3},{%4,%5,%6,%7},{%8,%9},{%0,%1,%2,%3};"
        : "+f"(c[0]), "+f"(c[1]), "+f"(c[2]), "+f"(c[3])
        : "r"(a0), "r"(a1), "r"(a2), "r"(a3), "r"(b0), "r"(b1));
}

// ---------------------------------------------------------------------------
// Kernel A: Q = tf32( scale * (x1 @ W1^T + b1) )  via tf32 mma (64x128x128)
// 8 warps: warp w -> m-tile (w&3)*16, n-base (w>>2)*64, 8 n-tiles of 8
// ---------------------------------------------------------------------------
#define QK_SMEM_FLOATS (8448 + 4608)   // a_s[64][132] + w_s[128][36]

__global__ void __launch_bounds__(256) q_kernel(
    const float* __restrict__ x1, const float* __restrict__ w1,
    const float* __restrict__ bias1)
{
    extern __shared__ float sm[];
    float* a_s = sm;          // [m][k] stride 132
    float* w_s = sm + 8448;   // [j][kk] stride 36

    const int t = threadIdx.x, b = blockIdx.x;
    const int lane = t & 31, wid = t >> 5;
    const int m_base = (wid & 3) * 16;
    const int n_base = (wid >> 2) * 64;
    const int r0 = lane >> 2, cth = lane & 3;

    const float* xb = x1 + (size_t)b * (NTOK * DIM);
    for (int idx = t; idx < NTOK * DIM; idx += 256) {
        int m = idx >> 7, k = idx & 127;
        a_s[m * 132 + k] = to_tf32(xb[idx]);
    }

    float c[8][4];
#pragma unroll
    for (int nt = 0; nt < 8; nt++)
#pragma unroll
        for (int j = 0; j < 4; j++) c[nt][j] = 0.f;

    for (int kc = 0; kc < 4; kc++) {
        __syncthreads();
        for (int idx = t; idx < 4096; idx += 256) {
            int j = idx >> 5, kk = idx & 31;
            w_s[j * 36 + kk] = to_tf32(w1[j * DIM + kc * 32 + kk]);
        }
        __syncthreads();
#pragma unroll
        for (int ks = 0; ks < 4; ks++) {
            const int col = kc * 32 + ks * 8 + cth;
            const uint32_t a0 = __float_as_uint(a_s[(m_base + r0) * 132 + col]);
            const uint32_t a1 = __float_as_uint(a_s[(m_base + r0 + 8) * 132 + col]);
            const uint32_t a2 = __float_as_uint(a_s[(m_base + r0) * 132 + col + 4]);
            const uint32_t a3 = __float_as_uint(a_s[(m_base + r0 + 8) * 132 + col + 4]);
#pragma unroll
            for (int nt = 0; nt < 8; nt++) {
                const int j = n_base + nt * 8 + r0;
                const uint32_t b0 = __float_as_uint(w_s[j * 36 + ks * 8 + cth]);
                const uint32_t b1 = __float_as_uint(w_s[j * 36 + ks * 8 + 4 + cth]);
                mma_tf32(c[nt], a0, a1, a2, a3, b0, b1);
            }
        }
    }

    float* qb = g_Q + (size_t)b * (NTOK * DIM);
    const int row0 = m_base + r0;
#pragma unroll
    for (int nt = 0; nt < 8; nt++) {
        const int col0 = n_base + nt * 8 + 2 * cth;
        const float2 bv = *(const float2*)(bias1 + col0);
        *(float2*)(qb + (size_t)row0 * DIM + col0) =
            make_float2(to_tf32((c[nt][0] + bv.x) * QSCALE),
                        to_tf32((c[nt][1] + bv.y) * QSCALE));
        *(float2*)(qb + (size_t)(row0 + 8) * DIM + col0) =
            make_float2(to_tf32((c[nt][2] + bv.x) * QSCALE),
                        to_tf32((c[nt][3] + bv.y) * QSCALE));
    }
}

// ---------------------------------------------------------------------------
// Kernel B: KV[b2] = tf32( x2[b2] @ W2^T + b2 )  via tf32 mma (64x256x128)
// ---------------------------------------------------------------------------
#define KV_SMEM_FLOATS (8448 + 9216)   // a_s[64][132] + w_s[256][36]

__global__ void __launch_bounds__(256) kv_kernel(
    const float* __restrict__ x2, const float* __restrict__ w2,
    const float* __restrict__ bias2)
{
    extern __shared__ float sm[];
    float* a_s = sm;
    float* w_s = sm + 8448;

    const int t = threadIdx.x, b2 = blockIdx.x;
    const int lane = t & 31, wid = t >> 5;
    const int m_base = (wid & 3) * 16;
    const int n_base = (wid >> 2) * 128;
    const int r0 = lane >> 2, cth = lane & 3;

    const float* xb = x2 + (size_t)b2 * (NTOK * DIM);
    for (int idx = t; idx < NTOK * DIM; idx += 256) {
        int m = idx >> 7, k = idx & 127;
        a_s[m * 132 + k] = to_tf32(xb[idx]);
    }

    float c[16][4];
#pragma unroll
    for (int nt = 0; nt < 16; nt++)
#pragma unroll
        for (int j = 0; j < 4; j++) c[nt][j] = 0.f;

    for (int kc = 0; kc < 4; kc++) {
        __syncthreads();
        for (int idx = t; idx < 8192; idx += 256) {
            int j = idx >> 5, kk = idx & 31;
            w_s[j * 36 + kk] = to_tf32(w2[j * DIM + kc * 32 + kk]);
        }
        __syncthreads();
#pragma unroll
        for (int ks = 0; ks < 4; ks++) {
            const int col = kc * 32 + ks * 8 + cth;
            const uint32_t a0 = __float_as_uint(a_s[(m_base + r0) * 132 + col]);
            const uint32_t a1 = __float_as_uint(a_s[(m_base + r0 + 8) * 132 + col]);
            const uint32_t a2 = __float_as_uint(a_s[(m_base + r0) * 132 + col + 4]);
            const uint32_t a3 = __float_as_uint(a_s[(m_base + r0 + 8) * 132 + col + 4]);
#pragma unroll
            for (int nt = 0; nt < 16; nt++) {
                const int j = n_base + nt * 8 + r0;
                const uint32_t b0 = __float_as_uint(w_s[j * 36 + ks * 8 + cth]);
                const uint32_t b1 = __float_as_uint(w_s[j * 36 + ks * 8 + 4 + cth]);
                mma_tf32(c[nt], a0, a1, a2, a3, b0, b1);
            }
        }
    }

    float* dst = g_KV + (size_t)b2 * (NTOK * 256);
    const int row0 = m_base + r0;
#pragma unroll
    for (int nt = 0; nt < 16; nt++) {
        const int col0 = n_base + nt * 8 + 2 * cth;
        const float2 bv = *(const float2*)(bias2 + col0);
        *(float2*)(dst + (size_t)row0 * 256 + col0) =
            make_float2(to_tf32(c[nt][0] + bv.x), to_tf32(c[nt][1] + bv.y));
        *(float2*)(dst + (size_t)(row0 + 8) * 256 + col0) =
            make_float2(to_tf32(c[nt][2] + bv.x), to_tf32(c[nt][3] + bv.y));
    }
}

// ---------------------------------------------------------------------------
// Kernel C: fused attention per b1 using tf32 mma for QK^T and PV.
// 512 threads = 16 warps; warp w: head h = w>>2, row-slab R0 = (w&3)*16.
// ---------------------------------------------------------------------------
#define SMQ   0        // q_s [n][132] : 8448
#define SMK   8448     // k_s [m][132] : 8448
#define SMV   16896    // v_s [m][132] : 8448
#define SMREL 25344    // uint16[64*64] : 2048 floats
#define SMTAB 27392    // 225*4 : 900
#define ATTN_SMEM_FLOATS 28292
// oT (128x68 = 8704) aliases q_s+k_s; pwT (32x132 = 4224) aliases v_s

__global__ void __launch_bounds__(512, 1) attn_kernel(
    const float* __restrict__ pw, const float* __restrict__ pb,
    const float* __restrict__ rpb, const int* __restrict__ rel,
    float* __restrict__ out)
{
    extern __shared__ float sm[];
    float*    q_s   = sm + SMQ;
    float*    k_s   = sm + SMK;
    float*    v_s   = sm + SMV;
    uint16_t* rel_s = (uint16_t*)(sm + SMREL);
    float*    tab_s = sm + SMTAB;
    float*    oT    = sm;          // after r-loop
    float*    pwT   = sm + SMV;    // after r-loop

    const int t    = threadIdx.x;
    const int bdst = blockIdx.x;
    const int lane = t & 31, wid = t >> 5;
    const int h  = wid >> 2;
    const int R0 = (wid & 3) * 16;
    const int r0 = lane >> 2, cth = lane & 3;
    const int n_lo = R0 + r0, n_hi = n_lo + 8;

    for (int idx = t; idx < NTOK * NTOK; idx += 512)
        rel_s[idx] = (uint16_t)rel[idx];
    for (int idx = t; idx < 225 * 4; idx += 512)
        tab_s[idx] = rpb[idx];

    float oacc[4][4];
#pragma unroll
    for (int nt = 0; nt < 4; nt++)
#pragma unroll
        for (int j = 0; j < 4; j++) oacc[nt][j] = 0.f;

    for (int r = 0; r < 4; r++) {
        const int b2 = bdst * 4 + r;
        const int qb = b2 & (B1N - 1);

        __syncthreads();

        // stage Q (already tf32+scaled) 64x128 -> stride 132
        const float4* qg = (const float4*)(g_Q + (size_t)qb * (NTOK * DIM));
        for (int idx = t; idx < 2048; idx += 512) {
            int nn = idx >> 5, c4 = idx & 31;
            *(float4*)&q_s[nn * 132 + c4 * 4] = qg[idx];
        }
        // stage K,V (already tf32) from g_KV[b2]
        const float4* kvg = (const float4*)(g_KV + (size_t)b2 * (NTOK * 256));
        for (int idx = t; idx < 4096; idx += 512) {
            int m = idx >> 6, j4 = idx & 63;
            float4 v = kvg[idx];
            if (j4 < 32) *(float4*)&k_s[m * 132 + j4 * 4] = v;
            else         *(float4*)&v_s[m * 132 + (j4 - 32) * 4] = v;
        }
        __syncthreads();

        // ---- S = Q K^T  (warp: 16 rows x 64 cols) ----
        float c[8][4];
#pragma unroll
        for (int nt = 0; nt < 8; nt++)
#pragma unroll
            for (int j = 0; j < 4; j++) c[nt][j] = 0.f;

#pragma unroll
        for (int ks = 0; ks < 4; ks++) {
            const int col = h * 32 + ks * 8 + cth;
            const uint32_t a0 = __float_as_uint(q_s[n_lo * 132 + col]);
            const uint32_t a1 = __float_as_uint(q_s[n_hi * 132 + col]);
            const uint32_t a2 = __float_as_uint(q_s[n_lo * 132 + col + 4]);
            const uint32_t a3 = __float_as_uint(q_s[n_hi * 132 + col + 4]);
#pragma unroll
            for (int nt = 0; nt < 8; nt++) {
                const int m = nt * 8 + r0;
                const uint32_t b0 = __float_as_uint(k_s[m * 132 + col]);
                const uint32_t b1 = __float_as_uint(k_s[m * 132 + col + 4]);
                mma_tf32(c[nt], a0, a1, a2, a3, b0, b1);
            }
        }

        // ---- + relative position bias ----
#pragma unroll
        for (int nt = 0; nt < 8; nt++) {
            const int m = nt * 8 + 2 * cth;
            const uint32_t rlo = *(const uint32_t*)&rel_s[n_lo * 64 + m];
            const uint32_t rhi = *(const uint32_t*)&rel_s[n_hi * 64 + m];
            c[nt][0] += tab_s[(rlo & 0xffff) * 4 + h];
            c[nt][1] += tab_s[(rlo >> 16) * 4 + h];
            c[nt][2] += tab_s[(rhi & 0xffff) * 4 + h];
            c[nt][3] += tab_s[(rhi >> 16) * 4 + h];
        }

        // ---- softmax (rows n_lo, n_hi; quad reduce over cth lanes) ----
        float mx0 = -1e30f, mx1 = -1e30f;
#pragma unroll
        for (int nt = 0; nt < 8; nt++) {
            mx0 = fmaxf(mx0, fmaxf(c[nt][0], c[nt][1]));
            mx1 = fmaxf(mx1, fmaxf(c[nt][2], c[nt][3]));
        }
        mx0 = fmaxf(mx0, __shfl_xor_sync(0xffffffffu, mx0, 1));
        mx0 = fmaxf(mx0, __shfl_xor_sync(0xffffffffu, mx0, 2));
        mx1 = fmaxf(mx1, __shfl_xor_sync(0xffffffffu, mx1, 1));
        mx1 = fmaxf(mx1, __shfl_xor_sync(0xffffffffu, mx1, 2));

        float s0 = 0.f, s1 = 0.f;
#pragma unroll
        for (int nt = 0; nt < 8; nt++) {
            c[nt][0] = __expf(c[nt][0] - mx0); s0 += c[nt][0];
            c[nt][1] = __expf(c[nt][1] - mx0); s0 += c[nt][1];
            c[nt][2] = __expf(c[nt][2] - mx1); s1 += c[nt][2];
            c[nt][3] = __expf(c[nt][3] - mx1); s1 += c[nt][3];
        }
        s0 += __shfl_xor_sync(0xffffffffu, s0, 1);
        s0 += __shfl_xor_sync(0xffffffffu, s0, 2);
        s1 += __shfl_xor_sync(0xffffffffu, s1, 1);
        s1 += __shfl_xor_sync(0xffffffffu, s1, 2);
        const float inv0 = 1.f / s0, inv1 = 1.f / s1;
#pragma unroll
        for (int nt = 0; nt < 8; nt++) {
            c[nt][0] *= inv0; c[nt][1] *= inv0;
            c[nt][2] *= inv1; c[nt][3] *= inv1;
        }

        // ---- write attn probs (full fp32) ----
        float* ao = out + (size_t)X_ELEMS + (size_t)b2 * 16384 + h * 4096;
#pragma unroll
        for (int nt = 0; nt < 8; nt++) {
            const int m = nt * 8 + 2 * cth;
            *(float2*)&ao[n_lo * 64 + m] = make_float2(c[nt][0], c[nt][1]);
            *(float2*)&ao[n_hi * 64 + m] = make_float2(c[nt][2], c[nt][3]);
        }

        // ---- round P to tf32, convert C-frag -> A-frag via shuffles, PV mma ----
#pragma unroll
        for (int nt = 0; nt < 8; nt++)
#pragma unroll
            for (int j = 0; j < 4; j++) c[nt][j] = to_tf32(c[nt][j]);

        const int src0 = (lane & 28) + (cth >> 1);
        const int src1 = src0 + 2;
        const bool odd = (cth & 1);
#pragma unroll
        for (int ks = 0; ks < 8; ks++) {
            const float e0 = __shfl_sync(0xffffffffu, c[ks][0], src0);
            const float o0 = __shfl_sync(0xffffffffu, c[ks][1], src0);
            const float e2 = __shfl_sync(0xffffffffu, c[ks][0], src1);
            const float o2 = __shfl_sync(0xffffffffu, c[ks][1], src1);
            const float e1 = __shfl_sync(0xffffffffu, c[ks][2], src0);
            const float o1 = __shfl_sync(0xffffffffu, c[ks][3], src0);
            const float e3 = __shfl_sync(0xffffffffu, c[ks][2], src1);
            const float o3 = __shfl_sync(0xffffffffu, c[ks][3], src1);
            const uint32_t pa0 = __float_as_uint(odd ? o0 : e0);
            const uint32_t pa1 = __float_as_uint(odd ? o1 : e1);
            const uint32_t pa2 = __float_as_uint(odd ? o2 : e2);
            const uint32_t pa3 = __float_as_uint(odd ? o3 : e3);
            const int mrow = ks * 8 + cth;
#pragma unroll
            for (int nt = 0; nt < 4; nt++) {
                const int dcol = h * 32 + nt * 8 + r0;
                const uint32_t b0 = __float_as_uint(v_s[mrow * 132 + dcol]);
                const uint32_t b1 = __float_as_uint(v_s[(mrow + 4) * 132 + dcol]);
                mma_tf32(oacc[nt], pa0, pa1, pa2, pa3, b0, b1);
            }
        }
    } // r

    // ---- park O transposed [c][n] in smem, then output projection ----
    __syncthreads();
#pragma unroll
    for (int nt = 0; nt < 4; nt++) {
        const int d0 = h * 32 + nt * 8 + 2 * cth;
        oT[d0 * 68 + n_lo]       = oacc[nt][0];
        oT[(d0 + 1) * 68 + n_lo] = oacc[nt][1];
        oT[d0 * 68 + n_hi]       = oacc[nt][2];
        oT[(d0 + 1) * 68 + n_hi] = oacc[nt][3];
    }

    const int ty = t >> 5, tx = t & 31;
    float pacc[4][4];
#pragma unroll
    for (int i = 0; i < 4; i++)
#pragma unroll
        for (int j = 0; j < 4; j++) pacc[i][j] = 0.f;

    for (int k0 = 0; k0 < DIM; k0 += 32) {
        __syncthreads();
        for (int idx = t; idx < DIM * 32; idx += 512) {
            int j = idx >> 5, kk = idx & 31;
            pwT[kk * 132 + j] = pw[j * DIM + k0 + kk];
        }
        __syncthreads();
#pragma unroll
        for (int kk = 0; kk < 32; kk++) {
            const float4 a4 = *(const float4*)&oT[(k0 + kk) * 68 + ty * 4];
            const float4 b4 = *(const float4*)&pwT[kk * 132 + tx * 4];
            const float av[4] = {a4.x, a4.y, a4.z, a4.w};
            const float bv[4] = {b4.x, b4.y, b4.z, b4.w};
#pragma unroll
            for (int i = 0; i < 4; i++)
#pragma unroll
                for (int j = 0; j < 4; j++) pacc[i][j] += av[i] * bv[j];
        }
    }

    const float pb0 = pb[tx * 4 + 0], pb1 = pb[tx * 4 + 1];
    const float pb2 = pb[tx * 4 + 2], pb3 = pb[tx * 4 + 3];
    float* xo = out + (size_t)bdst * (NTOK * DIM);
#pragma unroll
    for (int i = 0; i < 4; i++) {
        float4 o;
        o.x = pacc[i][0] + pb0;
        o.y = pacc[i][1] + pb1;
        o.z = pacc[i][2] + pb2;
        o.w = pacc[i][3] + pb3;
        *(float4*)&xo[(ty * 4 + i) * DIM + tx * 4] = o;
    }
}

// ---------------------------------------------------------------------------
extern "C" void kernel_launch(void* const* d_in, const int* in_sizes, int n_in,
                              void* d_out, int out_size)
{
    const float* x1     = (const float*)d_in[0];
    const float* x2     = (const float*)d_in[1];
    const float* qkv1_w = (const float*)d_in[2];
    const float* qkv1_b = (const float*)d_in[3];
    const float* qkv2_w = (const float*)d_in[4];
    const float* qkv2_b = (const float*)d_in[5];
    const float* proj_w = (const float*)d_in[6];
    const float* proj_b = (const float*)d_in[7];
    const float* rpb    = (const float*)d_in[8];
    const int*   rel    = (const int*)d_in[9];
    float* out = (float*)d_out;

    static bool attr_set = false;
    if (!attr_set) {
        cudaFuncSetAttribute(q_kernel,
                             cudaFuncAttributeMaxDynamicSharedMemorySize,
                             QK_SMEM_FLOATS * sizeof(float));
        cudaFuncSetAttribute(kv_kernel,
                             cudaFuncAttributeMaxDynamicSharedMemorySize,
                             KV_SMEM_FLOATS * sizeof(float));
        cudaFuncSetAttribute(attn_kernel,
                             cudaFuncAttributeMaxDynamicSharedMemorySize,
                             ATTN_SMEM_FLOATS * sizeof(float));
        attr_set = true;
    }

    q_kernel<<<B1N, 256, QK_SMEM_FLOATS * sizeof(float)>>>(x1, qkv1_w, qkv1_b);
    kv_kernel<<<B2N, 256, KV_SMEM_FLOATS * sizeof(float)>>>(x2, qkv2_w, qkv2_b);
    attn_kernel<<<B1N, 512, ATTN_SMEM_FLOATS * sizeof(float)>>>(
        proj_w, proj_b, rpb, rel, out);
}

// round 7
// speedup vs baseline: 2.6766x; 1.0975x over previous
#include <cuda_runtime.h>
#include <cstdint>

#define NTOK 64
#define DIM  128
#define B1N  2048
#define B2N  8192
#define QSCALE 0.17677669529663687f
#define X_ELEMS 16777216   // B1N*NTOK*DIM

__device__ float g_Q[B1N * NTOK * DIM];                 // tf32-rounded, scaled
__device__ float g_KV[(size_t)B2N * NTOK * 256];        // tf32-rounded K|V

__device__ __forceinline__ float to_tf32(float x) {
    float r; asm("cvt.rna.tf32.f32 %0, %1;" : "=f"(r) : "f"(x)); return r;
}
__device__ __forceinline__ void mma_tf32(float c[4],
    uint32_t a0, uint32_t a1, uint32_t a2, uint32_t a3,
    uint32_t b0, uint32_t b1)
{
    asm volatile(
        "mma.sync.aligned.m16n8k8.row.col.f32.tf32.tf32.f32 "
        "{%0,%1,%2,%3},{%4,%5,%6,%7},{%8,%9},{%0,%1,%2,%3};"
        : "+f"(c[0]), "+f"(c[1]), "+f"(c[2]), "+f"(c[3])
        : "r"(a0), "r"(a1), "r"(a2), "r"(a3), "r"(b0), "r"(b1));
}

__device__ __forceinline__ uint32_t smem_u32(const void* p) {
    return (uint32_t)__cvta_generic_to_shared(p);
}
__device__ __forceinline__ void cp16(uint32_t dst, const void* src) {
    asm volatile("cp.async.cg.shared.global [%0], [%1], 16;" :: "r"(dst), "l"(src));
}
#define CP_COMMIT() asm volatile("cp.async.commit_group;")
#define CP_WAIT0()  asm volatile("cp.async.wait_group 0;")
#define CP_WAIT1()  asm volatile("cp.async.wait_group 1;")

// ---------------------------------------------------------------------------
// Kernel A: Q = tf32( scale * (x1 @ W1^T + b1) )  via tf32 mma (64x128x128)
// ---------------------------------------------------------------------------
#define QK_SMEM_FLOATS (8448 + 4608)   // a_s[64][132] + w_s[128][36]

__global__ void __launch_bounds__(256) q_kernel(
    const float* __restrict__ x1, const float* __restrict__ w1,
    const float* __restrict__ bias1)
{
    extern __shared__ float sm[];
    float* a_s = sm;          // [m][k] stride 132
    float* w_s = sm + 8448;   // [j][kk] stride 36

    const int t = threadIdx.x, b = blockIdx.x;
    const int lane = t & 31, wid = t >> 5;
    const int m_base = (wid & 3) * 16;
    const int n_base = (wid >> 2) * 64;
    const int r0 = lane >> 2, cth = lane & 3;

    const float* xb = x1 + (size_t)b * (NTOK * DIM);
    for (int idx = t; idx < NTOK * DIM; idx += 256) {
        int m = idx >> 7, k = idx & 127;
        a_s[m * 132 + k] = to_tf32(xb[idx]);
    }

    float c[8][4];
#pragma unroll
    for (int nt = 0; nt < 8; nt++)
#pragma unroll
        for (int j = 0; j < 4; j++) c[nt][j] = 0.f;

    for (int kc = 0; kc < 4; kc++) {
        __syncthreads();
        for (int idx = t; idx < 4096; idx += 256) {
            int j = idx >> 5, kk = idx & 31;
            w_s[j * 36 + kk] = to_tf32(w1[j * DIM + kc * 32 + kk]);
        }
        __syncthreads();
#pragma unroll
        for (int ks = 0; ks < 4; ks++) {
            const int col = kc * 32 + ks * 8 + cth;
            const uint32_t a0 = __float_as_uint(a_s[(m_base + r0) * 132 + col]);
            const uint32_t a1 = __float_as_uint(a_s[(m_base + r0 + 8) * 132 + col]);
            const uint32_t a2 = __float_as_uint(a_s[(m_base + r0) * 132 + col + 4]);
            const uint32_t a3 = __float_as_uint(a_s[(m_base + r0 + 8) * 132 + col + 4]);
#pragma unroll
            for (int nt = 0; nt < 8; nt++) {
                const int j = n_base + nt * 8 + r0;
                const uint32_t b0 = __float_as_uint(w_s[j * 36 + ks * 8 + cth]);
                const uint32_t b1 = __float_as_uint(w_s[j * 36 + ks * 8 + 4 + cth]);
                mma_tf32(c[nt], a0, a1, a2, a3, b0, b1);
            }
        }
    }

    float* qb = g_Q + (size_t)b * (NTOK * DIM);
    const int row0 = m_base + r0;
#pragma unroll
    for (int nt = 0; nt < 8; nt++) {
        const int col0 = n_base + nt * 8 + 2 * cth;
        const float2 bv = *(const float2*)(bias1 + col0);
        *(float2*)(qb + (size_t)row0 * DIM + col0) =
            make_float2(to_tf32((c[nt][0] + bv.x) * QSCALE),
                        to_tf32((c[nt][1] + bv.y) * QSCALE));
        *(float2*)(qb + (size_t)(row0 + 8) * DIM + col0) =
            make_float2(to_tf32((c[nt][2] + bv.x) * QSCALE),
                        to_tf32((c[nt][3] + bv.y) * QSCALE));
    }
}

// ---------------------------------------------------------------------------
// Kernel B: KV[b2] = tf32( x2[b2] @ W2^T + b2 )  via tf32 mma (64x256x128)
// 512 threads, 16 warps: warp w -> m-tile (w&3)*16, n-base (w>>2)*64, 8 nt
// ---------------------------------------------------------------------------
#define KV_SMEM_FLOATS (8448 + 9216)   // a_s[64][132] + w_s[256][36]

__global__ void __launch_bounds__(512, 2) kv_kernel(
    const float* __restrict__ x2, const float* __restrict__ w2,
    const float* __restrict__ bias2)
{
    extern __shared__ float sm[];
    float* a_s = sm;
    float* w_s = sm + 8448;

    const int t = threadIdx.x, b2 = blockIdx.x;
    const int lane = t & 31, wid = t >> 5;
    const int m_base = (wid & 3) * 16;
    const int n_base = (wid >> 2) * 64;
    const int r0 = lane >> 2, cth = lane & 3;

    const float* xb = x2 + (size_t)b2 * (NTOK * DIM);
    for (int idx = t; idx < NTOK * DIM; idx += 512) {
        int m = idx >> 7, k = idx & 127;
        a_s[m * 132 + k] = to_tf32(xb[idx]);
    }

    float c[8][4];
#pragma unroll
    for (int nt = 0; nt < 8; nt++)
#pragma unroll
        for (int j = 0; j < 4; j++) c[nt][j] = 0.f;

    for (int kc = 0; kc < 4; kc++) {
        __syncthreads();
        for (int idx = t; idx < 8192; idx += 512) {
            int j = idx >> 5, kk = idx & 31;
            w_s[j * 36 + kk] = to_tf32(w2[j * DIM + kc * 32 + kk]);
        }
        __syncthreads();
#pragma unroll
        for (int ks = 0; ks < 4; ks++) {
            const int col = kc * 32 + ks * 8 + cth;
            const uint32_t a0 = __float_as_uint(a_s[(m_base + r0) * 132 + col]);
            const uint32_t a1 = __float_as_uint(a_s[(m_base + r0 + 8) * 132 + col]);
            const uint32_t a2 = __float_as_uint(a_s[(m_base + r0) * 132 + col + 4]);
            const uint32_t a3 = __float_as_uint(a_s[(m_base + r0 + 8) * 132 + col + 4]);
#pragma unroll
            for (int nt = 0; nt < 8; nt++) {
                const int j = n_base + nt * 8 + r0;
                const uint32_t b0 = __float_as_uint(w_s[j * 36 + ks * 8 + cth]);
                const uint32_t b1 = __float_as_uint(w_s[j * 36 + ks * 8 + 4 + cth]);
                mma_tf32(c[nt], a0, a1, a2, a3, b0, b1);
            }
        }
    }

    float* dst = g_KV + (size_t)b2 * (NTOK * 256);
    const int row0 = m_base + r0;
#pragma unroll
    for (int nt = 0; nt < 8; nt++) {
        const int col0 = n_base + nt * 8 + 2 * cth;
        const float2 bv = *(const float2*)(bias2 + col0);
        *(float2*)(dst + (size_t)row0 * 256 + col0) =
            make_float2(to_tf32(c[nt][0] + bv.x), to_tf32(c[nt][1] + bv.y));
        *(float2*)(dst + (size_t)(row0 + 8) * 256 + col0) =
            make_float2(to_tf32(c[nt][2] + bv.x), to_tf32(c[nt][3] + bv.y));
    }
}

// ---------------------------------------------------------------------------
// Kernel C: fused attention per b1, tf32 mma for QK^T and PV.
// cp.async DOUBLE-BUFFERED staging of Q/K/V across the r-loop.
// 512 threads = 16 warps; warp w: head h = w>>2, row-slab R0 = (w&3)*16.
// ---------------------------------------------------------------------------
// stage layout (floats): q [64][132]=8448 | k [64][132]=8448 | v [64][132]=8448
#define STG_Q 0
#define STG_K 8448
#define STG_V 16896
#define STG_SZ 25344
#define SMREL (2 * STG_SZ)           // 50688 : uint16[4096] = 2048 floats
#define SMTAB (SMREL + 2048)         // 52736 : 225*4 = 900
#define ATTN_SMEM_FLOATS (SMTAB + 900)   // 53636 floats = 214544 B
// after r-loop: oT (128x68=8704) aliases stage0 [0..8704); pwT (32x132=4224) at stage0+8704

__device__ __forceinline__ void stage_issue(float* buf, int t, int qb, int b2)
{
    const float4* qg = (const float4*)(g_Q + (size_t)qb * (NTOK * DIM));
#pragma unroll
    for (int i = 0; i < 4; i++) {
        const int idx = t + i * 512;          // 0..2047
        const int nn = idx >> 5, c4 = idx & 31;
        cp16(smem_u32(buf + STG_Q + nn * 132 + c4 * 4), qg + idx);
    }
    const float4* kvg = (const float4*)(g_KV + (size_t)b2 * (NTOK * 256));
#pragma unroll
    for (int i = 0; i < 8; i++) {
        const int idx = t + i * 512;          // 0..4095
        const int m = idx >> 6, j4 = idx & 63;
        float* dst = (j4 < 32) ? buf + STG_K + m * 132 + j4 * 4
                               : buf + STG_V + m * 132 + (j4 - 32) * 4;
        cp16(smem_u32(dst), kvg + idx);
    }
}

__global__ void __launch_bounds__(512, 1) attn_kernel(
    const float* __restrict__ pw, const float* __restrict__ pb,
    const float* __restrict__ rpb, const int* __restrict__ rel,
    float* __restrict__ out)
{
    extern __shared__ float sm[];
    uint16_t* rel_s = (uint16_t*)(sm + SMREL);
    float*    tab_s = sm + SMTAB;
    float*    oT    = sm;           // after r-loop (stage 0 area)
    float*    pwT   = sm + 8704;    // after r-loop (stage 0 area)

    const int t    = threadIdx.x;
    const int bdst = blockIdx.x;
    const int lane = t & 31, wid = t >> 5;
    const int h  = wid >> 2;
    const int R0 = (wid & 3) * 16;
    const int r0 = lane >> 2, cth = lane & 3;
    const int n_lo = R0 + r0, n_hi = n_lo + 8;

    for (int idx = t; idx < NTOK * NTOK; idx += 512)
        rel_s[idx] = (uint16_t)rel[idx];
    for (int idx = t; idx < 225 * 4; idx += 512)
        tab_s[idx] = rpb[idx];

    // prologue: issue stage 0
    {
        const int b2 = bdst * 4;
        stage_issue(sm, t, b2 & (B1N - 1), b2);
        CP_COMMIT();
    }

    float oacc[4][4];
#pragma unroll
    for (int nt = 0; nt < 4; nt++)
#pragma unroll
        for (int j = 0; j < 4; j++) oacc[nt][j] = 0.f;

    for (int r = 0; r < 4; r++) {
        __syncthreads();   // buffer (r+1)&1 free (stage r-1 consumers done); rel/tab ready
        if (r < 3) {
            const int b2n = bdst * 4 + r + 1;
            stage_issue(sm + ((r + 1) & 1) * STG_SZ, t, b2n & (B1N - 1), b2n);
            CP_COMMIT();
            CP_WAIT1();    // stage r arrived (newest group still in flight)
        } else {
            CP_WAIT0();
        }
        __syncthreads();   // stage r visible to all

        float* q_s = sm + (r & 1) * STG_SZ + STG_Q;
        float* k_s = sm + (r & 1) * STG_SZ + STG_K;
        float* v_s = sm + (r & 1) * STG_SZ + STG_V;
        const int b2 = bdst * 4 + r;

        // ---- S = Q K^T  (warp: 16 rows x 64 cols) ----
        float c[8][4];
#pragma unroll
        for (int nt = 0; nt < 8; nt++)
#pragma unroll
            for (int j = 0; j < 4; j++) c[nt][j] = 0.f;

#pragma unroll
        for (int ks = 0; ks < 4; ks++) {
            const int col = h * 32 + ks * 8 + cth;
            const uint32_t a0 = __float_as_uint(q_s[n_lo * 132 + col]);
            const uint32_t a1 = __float_as_uint(q_s[n_hi * 132 + col]);
            const uint32_t a2 = __float_as_uint(q_s[n_lo * 132 + col + 4]);
            const uint32_t a3 = __float_as_uint(q_s[n_hi * 132 + col + 4]);
#pragma unroll
            for (int nt = 0; nt < 8; nt++) {
                const int m = nt * 8 + r0;
                const uint32_t b0 = __float_as_uint(k_s[m * 132 + col]);
                const uint32_t b1 = __float_as_uint(k_s[m * 132 + col + 4]);
                mma_tf32(c[nt], a0, a1, a2, a3, b0, b1);
            }
        }

        // ---- + relative position bias ----
#pragma unroll
        for (int nt = 0; nt < 8; nt++) {
            const int m = nt * 8 + 2 * cth;
            const uint32_t rlo = *(const uint32_t*)&rel_s[n_lo * 64 + m];
            const uint32_t rhi = *(const uint32_t*)&rel_s[n_hi * 64 + m];
            c[nt][0] += tab_s[(rlo & 0xffff) * 4 + h];
            c[nt][1] += tab_s[(rlo >> 16) * 4 + h];
            c[nt][2] += tab_s[(rhi & 0xffff) * 4 + h];
            c[nt][3] += tab_s[(rhi >> 16) * 4 + h];
        }

        // ---- softmax (rows n_lo, n_hi; quad reduce) ----
        float mx0 = -1e30f, mx1 = -1e30f;
#pragma unroll
        for (int nt = 0; nt < 8; nt++) {
            mx0 = fmaxf(mx0, fmaxf(c[nt][0], c[nt][1]));
            mx1 = fmaxf(mx1, fmaxf(c[nt][2], c[nt][3]));
        }
        mx0 = fmaxf(mx0, __shfl_xor_sync(0xffffffffu, mx0, 1));
        mx0 = fmaxf(mx0, __shfl_xor_sync(0xffffffffu, mx0, 2));
        mx1 = fmaxf(mx1, __shfl_xor_sync(0xffffffffu, mx1, 1));
        mx1 = fmaxf(mx1, __shfl_xor_sync(0xffffffffu, mx1, 2));

        float s0 = 0.f, s1 = 0.f;
#pragma unroll
        for (int nt = 0; nt < 8; nt++) {
            c[nt][0] = __expf(c[nt][0] - mx0); s0 += c[nt][0];
            c[nt][1] = __expf(c[nt][1] - mx0); s0 += c[nt][1];
            c[nt][2] = __expf(c[nt][2] - mx1); s1 += c[nt][2];
            c[nt][3] = __expf(c[nt][3] - mx1); s1 += c[nt][3];
        }
        s0 += __shfl_xor_sync(0xffffffffu, s0, 1);
        s0 += __shfl_xor_sync(0xffffffffu, s0, 2);
        s1 += __shfl_xor_sync(0xffffffffu, s1, 1);
        s1 += __shfl_xor_sync(0xffffffffu, s1, 2);
        const float inv0 = 1.f / s0, inv1 = 1.f / s1;
#pragma unroll
        for (int nt = 0; nt < 8; nt++) {
            c[nt][0] *= inv0; c[nt][1] *= inv0;
            c[nt][2] *= inv1; c[nt][3] *= inv1;
        }

        // ---- write attn probs ----
        float* ao = out + (size_t)X_ELEMS + (size_t)b2 * 16384 + h * 4096;
#pragma unroll
        for (int nt = 0; nt < 8; nt++) {
            const int m = nt * 8 + 2 * cth;
            *(float2*)&ao[n_lo * 64 + m] = make_float2(c[nt][0], c[nt][1]);
            *(float2*)&ao[n_hi * 64 + m] = make_float2(c[nt][2], c[nt][3]);
        }

        // ---- round P to tf32, C-frag -> A-frag shuffles, PV mma ----
#pragma unroll
        for (int nt = 0; nt < 8; nt++)
#pragma unroll
            for (int j = 0; j < 4; j++) c[nt][j] = to_tf32(c[nt][j]);

        const int src0 = (lane & 28) + (cth >> 1);
        const int src1 = src0 + 2;
        const bool odd = (cth & 1);
#pragma unroll
        for (int ks = 0; ks < 8; ks++) {
            const float e0 = __shfl_sync(0xffffffffu, c[ks][0], src0);
            const float o0 = __shfl_sync(0xffffffffu, c[ks][1], src0);
            const float e2 = __shfl_sync(0xffffffffu, c[ks][0], src1);
            const float o2 = __shfl_sync(0xffffffffu, c[ks][1], src1);
            const float e1 = __shfl_sync(0xffffffffu, c[ks][2], src0);
            const float o1 = __shfl_sync(0xffffffffu, c[ks][3], src0);
            const float e3 = __shfl_sync(0xffffffffu, c[ks][2], src1);
            const float o3 = __shfl_sync(0xffffffffu, c[ks][3], src1);
            const uint32_t pa0 = __float_as_uint(odd ? o0 : e0);
            const uint32_t pa1 = __float_as_uint(odd ? o1 : e1);
            const uint32_t pa2 = __float_as_uint(odd ? o2 : e2);
            const uint32_t pa3 = __float_as_uint(odd ? o3 : e3);
            const int mrow = ks * 8 + cth;
#pragma unroll
            for (int nt = 0; nt < 4; nt++) {
                const int dcol = h * 32 + nt * 8 + r0;
                const uint32_t b0 = __float_as_uint(v_s[mrow * 132 + dcol]);
                const uint32_t b1 = __float_as_uint(v_s[(mrow + 4) * 132 + dcol]);
                mma_tf32(oacc[nt], pa0, pa1, pa2, pa3, b0, b1);
            }
        }
    } // r

    // ---- park O transposed [c][n] in smem (stage-0 area), then projection ----
    __syncthreads();
#pragma unroll
    for (int nt = 0; nt < 4; nt++) {
        const int d0 = h * 32 + nt * 8 + 2 * cth;
        oT[d0 * 68 + n_lo]       = oacc[nt][0];
        oT[(d0 + 1) * 68 + n_lo] = oacc[nt][1];
        oT[d0 * 68 + n_hi]       = oacc[nt][2];
        oT[(d0 + 1) * 68 + n_hi] = oacc[nt][3];
    }

    const int ty = t >> 5, tx = t & 31;
    float pacc[4][4];
#pragma unroll
    for (int i = 0; i < 4; i++)
#pragma unroll
        for (int j = 0; j < 4; j++) pacc[i][j] = 0.f;

    for (int k0 = 0; k0 < DIM; k0 += 32) {
        __syncthreads();
        for (int idx = t; idx < DIM * 32; idx += 512) {
            int j = idx >> 5, kk = idx & 31;
            pwT[kk * 132 + j] = pw[j * DIM + k0 + kk];
        }
        __syncthreads();
#pragma unroll
        for (int kk = 0; kk < 32; kk++) {
            const float4 a4 = *(const float4*)&oT[(k0 + kk) * 68 + ty * 4];
            const float4 b4 = *(const float4*)&pwT[kk * 132 + tx * 4];
            const float av[4] = {a4.x, a4.y, a4.z, a4.w};
            const float bv[4] = {b4.x, b4.y, b4.z, b4.w};
#pragma unroll
            for (int i = 0; i < 4; i++)
#pragma unroll
                for (int j = 0; j < 4; j++) pacc[i][j] += av[i] * bv[j];
        }
    }

    const float pb0 = pb[tx * 4 + 0], pb1 = pb[tx * 4 + 1];
    const float pb2 = pb[tx * 4 + 2], pb3 = pb[tx * 4 + 3];
    float* xo = out + (size_t)bdst * (NTOK * DIM);
#pragma unroll
    for (int i = 0; i < 4; i++) {
        float4 o;
        o.x = pacc[i][0] + pb0;
        o.y = pacc[i][1] + pb1;
        o.z = pacc[i][2] + pb2;
        o.w = pacc[i][3] + pb3;
        *(float4*)&xo[(ty * 4 + i) * DIM + tx * 4] = o;
    }
}

// ---------------------------------------------------------------------------
extern "C" void kernel_launch(void* const* d_in, const int* in_sizes, int n_in,
                              void* d_out, int out_size)
{
    const float* x1     = (const float*)d_in[0];
    const float* x2     = (const float*)d_in[1];
    const float* qkv1_w = (const float*)d_in[2];
    const float* qkv1_b = (const float*)d_in[3];
    const float* qkv2_w = (const float*)d_in[4];
    const float* qkv2_b = (const float*)d_in[5];
    const float* proj_w = (const float*)d_in[6];
    const float* proj_b = (const float*)d_in[7];
    const float* rpb    = (const float*)d_in[8];
    const int*   rel    = (const int*)d_in[9];
    float* out = (float*)d_out;

    static bool attr_set = false;
    if (!attr_set) {
        cudaFuncSetAttribute(q_kernel,
                             cudaFuncAttributeMaxDynamicSharedMemorySize,
                             QK_SMEM_FLOATS * sizeof(float));
        cudaFuncSetAttribute(kv_kernel,
                             cudaFuncAttributeMaxDynamicSharedMemorySize,
                             KV_SMEM_FLOATS * sizeof(float));
        cudaFuncSetAttribute(attn_kernel,
                             cudaFuncAttributeMaxDynamicSharedMemorySize,
                             ATTN_SMEM_FLOATS * sizeof(float));
        attr_set = true;
    }

    q_kernel<<<B1N, 256, QK_SMEM_FLOATS * sizeof(float)>>>(x1, qkv1_w, qkv1_b);
    kv_kernel<<<B2N, 512, KV_SMEM_FLOATS * sizeof(float)>>>(x2, qkv2_w, qkv2_b);
    attn_kernel<<<B1N, 512, ATTN_SMEM_FLOATS * sizeof(float)>>>(
        proj_w, proj_b, rpb, rel, out);
}